// round 1
// baseline (speedup 1.0000x reference)
#include <cuda_runtime.h>
#include <cstdint>

#define OUT_F   11008
#define IN_F    4096
#define TOK     16
#define NSPLIT  16
#define KCHUNK  (IN_F / NSPLIT)     // 256
#define THREADS 128
#define OUTS_PER_CTA 256            // 4 warps * 64 outputs
#define GROUPS  (KCHUNK / 16)       // 16 groups of 16 k

// Deterministic K-split partial sums: [split][token][out]
__device__ float g_partial[(size_t)NSPLIT * TOK * OUT_F];

// ---- f32x2 helpers (Blackwell packed fp32) ----
__device__ __forceinline__ unsigned long long pack2(unsigned int lo, unsigned int hi) {
    unsigned long long d;
    asm("mov.b64 %0, {%1,%2};" : "=l"(d) : "r"(lo), "r"(hi));
    return d;
}
__device__ __forceinline__ unsigned long long fma2(unsigned long long a, unsigned long long b, unsigned long long c) {
    unsigned long long d;
    asm("fma.rn.f32x2 %0, %1, %2, %3;" : "=l"(d) : "l"(a), "l"(b), "l"(c));
    return d;
}
__device__ __forceinline__ unsigned long long add2(unsigned long long a, unsigned long long b) {
    unsigned long long d;
    asm("add.rn.f32x2 %0, %1, %2;" : "=l"(d) : "l"(a), "l"(b));
    return d;
}
__device__ __forceinline__ unsigned long long mul2(unsigned long long a, unsigned long long b) {
    unsigned long long d;
    asm("mul.rn.f32x2 %0, %1, %2;" : "=l"(d) : "l"(a), "l"(b));
    return d;
}
__device__ __forceinline__ void unpack2(unsigned long long v, float& lo, float& hi) {
    unsigned int l, h;
    asm("mov.b64 {%0,%1}, %2;" : "=r"(l), "=r"(h) : "l"(v));
    lo = __uint_as_float(l);
    hi = __uint_as_float(h);
}

// Dequant pair: q0,q1 in [0,15] -> {s*(q0-8), s*(q1-8)} packed f32x2.
// f = as_float(0x4B000000|q) = 2^23 + q exactly; f - 8388616 = q-8 exactly;
// * s = one rounding, bit-identical to reference scale*(q-8).
__device__ __forceinline__ unsigned long long dq2(int q0, int q1, unsigned long long m2, unsigned long long s2) {
    unsigned long long f = pack2(0x4B000000u | (unsigned)q0, 0x4B000000u | (unsigned)q1);
    return mul2(add2(f, m2), s2);
}

__global__ void __launch_bounds__(THREADS, 3)
qlin_main(const float* __restrict__ x,
          const int* __restrict__ qw,
          const float* __restrict__ scales)
{
    __shared__ float xs[TOK][KCHUNK];   // 16 KB, natural [token][k] layout
    const int k0 = blockIdx.y * KCHUNK;

    // Cooperative load of the x K-chunk (coalesced float4, conflict-free stores)
    {
        const int tid = threadIdx.x;
        #pragma unroll
        for (int i = 0; i < 8; i++) {
            int idx = tid + i * THREADS;       // 0..1023 float4 slots
            int t   = idx >> 6;                // 64 float4 per token row
            int kq  = idx & 63;
            float4 v = reinterpret_cast<const float4*>(x + (size_t)t * IN_F + k0)[kq];
            reinterpret_cast<float4*>(&xs[t][0])[kq] = v;
        }
    }
    __syncthreads();

    const int lane = threadIdx.x & 31;
    const int warp = threadIdx.x >> 5;
    const int oA   = blockIdx.x * OUTS_PER_CTA + warp * 64 + lane * 2;
    const int oB   = oA + 1;

    const int4*  qA = reinterpret_cast<const int4*>(qw + (size_t)oA * IN_F + k0);
    const int4*  qB = reinterpret_cast<const int4*>(qw + (size_t)oB * IN_F + k0);
    const float* sA = scales + (size_t)oA * (IN_F / 32) + (k0 / 32);
    const float* sB = scales + (size_t)oB * (IN_F / 32) + (k0 / 32);

    unsigned long long accA[TOK], accB[TOK];
    #pragma unroll
    for (int t = 0; t < TOK; t++) { accA[t] = 0ULL; accB[t] = 0ULL; }

    const unsigned long long M2 =
        pack2(__float_as_uint(-8388616.0f), __float_as_uint(-8388616.0f));

    // Software pipeline over 16-k groups: 8 int4 prefetched per lane (MLP for HBM)
    int4 curA[4], curB[4], nxtA[4], nxtB[4];
    #pragma unroll
    for (int j = 0; j < 4; j++) { nxtA[j] = qA[j]; nxtB[j] = qB[j]; }

    #pragma unroll 1
    for (int g = 0; g < GROUPS; g++) {
        #pragma unroll
        for (int j = 0; j < 4; j++) { curA[j] = nxtA[j]; curB[j] = nxtB[j]; }
        int gn = (g + 1) & (GROUPS - 1);   // last iter harmlessly reloads group 0 (L1 hit)
        #pragma unroll
        for (int j = 0; j < 4; j++) {
            nxtA[j] = qA[gn * 4 + j];
            nxtB[j] = qB[gn * 4 + j];
        }

        float sa = sA[g >> 1];
        float sb = sB[g >> 1];
        unsigned long long sa2 = pack2(__float_as_uint(sa), __float_as_uint(sa));
        unsigned long long sb2 = pack2(__float_as_uint(sb), __float_as_uint(sb));

        #pragma unroll
        for (int j = 0; j < 4; j++) {
            int k = g * 16 + j * 4;
            unsigned long long wa01 = dq2(curA[j].x, curA[j].y, M2, sa2);
            unsigned long long wa23 = dq2(curA[j].z, curA[j].w, M2, sa2);
            unsigned long long wb01 = dq2(curB[j].x, curB[j].y, M2, sb2);
            unsigned long long wb23 = dq2(curB[j].z, curB[j].w, M2, sb2);
            #pragma unroll
            for (int t = 0; t < TOK; t++) {
                // broadcast LDS.128: all lanes read the same 16B
                ulonglong2 xv = *reinterpret_cast<const ulonglong2*>(&xs[t][k]);
                accA[t] = fma2(xv.x, wa01, accA[t]);
                accA[t] = fma2(xv.y, wa23, accA[t]);
                accB[t] = fma2(xv.x, wb01, accB[t]);
                accB[t] = fma2(xv.y, wb23, accB[t]);
            }
        }
    }

    // Epilogue: fold k-parity halves, store coalesced float2 partials
    float* out = g_partial + (size_t)blockIdx.y * TOK * OUT_F;
    #pragma unroll
    for (int t = 0; t < TOK; t++) {
        float aLo, aHi, bLo, bHi;
        unpack2(accA[t], aLo, aHi);
        unpack2(accB[t], bLo, bHi);
        float2 v = make_float2(aLo + aHi, bLo + bHi);
        *reinterpret_cast<float2*>(out + (size_t)t * OUT_F + oA) = v;
    }
}

__global__ void qlin_reduce(const float* __restrict__ bias, float* __restrict__ y)
{
    int o = blockIdx.x * 256 + threadIdx.x;
    int t = blockIdx.y;
    float acc = bias[o];
    #pragma unroll
    for (int s = 0; s < NSPLIT; s++)
        acc += g_partial[((size_t)s * TOK + t) * OUT_F + o];
    y[(size_t)t * OUT_F + o] = acc;
}

extern "C" void kernel_launch(void* const* d_in, const int* in_sizes, int n_in,
                              void* d_out, int out_size)
{
    const float* x      = (const float*)d_in[0];
    const int*   qw     = (const int*)d_in[1];
    const float* scales = (const float*)d_in[2];
    const float* bias   = (const float*)d_in[3];
    float*       y      = (float*)d_out;

    qlin_main  <<<dim3(43, NSPLIT), THREADS>>>(x, qw, scales);
    qlin_reduce<<<dim3(43, TOK),    256    >>>(bias, y);
}